// round 10
// baseline (speedup 1.0000x reference)
#include <cuda_runtime.h>

// result = 2*(C-1)/C^2 * mean(|ct|)  with C=8, H=W=512.
// Per pixel with target t, argmax q, value v:
//   sum_{c,l} |v*[l==t] - v*[c==q]| = 2*(C-1)*|v|, independent of t and q.
// pred_stage1 / target are never read; this is an abs-mean of ct.
//
// Single launch. Block partials are merged via ONE packed u64 atomicAdd:
//   bits [56:64) = arrival count, bits [0:56) = 2^30 fixed-point abs-sum.
// The atomic's return value gives the last arriver the full total directly:
// no __threadfence, no partials array, no second read. Integer adds commute
// exactly -> bit-deterministic output across replays.

#define NUM_BLOCKS  128
#define NUM_THREADS 256
#define FP_SCALE    1073741824.0   // 2^30

__device__ unsigned long long g_acc = 0ULL;

__global__ void __launch_bounds__(NUM_THREADS)
abs_mean_onepass(const float4* __restrict__ ct4, float scale,
                 float* __restrict__ out) {
    // 65536 float4s total -> 2 per thread, coalesced
    int base = blockIdx.x * (NUM_THREADS * 2) + threadIdx.x;
    float4 a = ct4[base];
    float4 b = ct4[base + NUM_THREADS];
    float s = fabsf(a.x) + fabsf(a.y) + fabsf(a.z) + fabsf(a.w)
            + fabsf(b.x) + fabsf(b.y) + fabsf(b.z) + fabsf(b.w);

    // warp reduce
    #pragma unroll
    for (int o = 16; o > 0; o >>= 1)
        s += __shfl_xor_sync(0xffffffffu, s, o);

    __shared__ float ws[NUM_THREADS / 32];
    if ((threadIdx.x & 31) == 0) ws[threadIdx.x >> 5] = s;
    __syncthreads();

    if (threadIdx.x == 0) {
        float bs = 0.0f;
        #pragma unroll
        for (int i = 0; i < NUM_THREADS / 32; i++) bs += ws[i];

        // pack: count in high byte, 2^30 fixed-point sum in low 56 bits.
        // per-block sum < ~4096*4 -> fixed < 2^44; x128 blocks < 2^51 < 2^56.
        unsigned long long fx =
            (unsigned long long)__double2ll_rn((double)bs * FP_SCALE);
        unsigned long long pkt = (1ULL << 56) | fx;
        unsigned long long old = atomicAdd(&g_acc, pkt);

        if ((old >> 56) == (unsigned long long)(NUM_BLOCKS - 1)) {
            unsigned long long total =
                (old & ((1ULL << 56) - 1ULL)) + fx;
            out[0] = (float)((double)total * (1.0 / FP_SCALE) * (double)scale);
            g_acc = 0ULL;  // reset for next graph replay (kernel-exit flush)
        }
    }
}

extern "C" void kernel_launch(void* const* d_in, const int* in_sizes, int n_in,
                              void* d_out, int out_size) {
    // inputs: [0] pred_stage1 f32 (unused), [1] ct f32, [2] target i64 (unused)
    const float* ct = (const float*)d_in[1];
    int n = in_sizes[1];  // 262144

    const int C = 8;
    float scale = (2.0f * (C - 1)) / ((float)(C * C)) / (float)n;

    abs_mean_onepass<<<NUM_BLOCKS, NUM_THREADS>>>((const float4*)ct, scale,
                                                  (float*)d_out);
}